// round 2
// baseline (speedup 1.0000x reference)
#include <cuda_runtime.h>

// Problem constants
#define Bb   2
#define Nn   2048
#define Dd   1024
#define Hh   16
#define DHd  64
#define HALFW 64          // window half-width; band is |i-j| <= 64 (129 keys)

#define QKV_COLS (3*Dd)   // 3072

// Scratch (device globals; no allocation allowed)
__device__ float g_qkv[(size_t)Bb*Nn*QKV_COLS];  // [B*N, 3072]
__device__ float g_att[(size_t)Bb*Nn*Dd];        // [B*N, 1024]

// ---------------------------------------------------------------------------
// SGEMM: C[M,N] = A[M,K] @ W[K,N] + bias[N]
// BM=128, BN=64, BK=16, 256 threads, 8x4 micro-tile per thread.
// Assumes M%128==0, N%64==0, K%16==0 (true for all calls here).
// ---------------------------------------------------------------------------
#define ASTRIDE 132  // padded A-smem row stride (floats), keeps 16B alignment, 2-way STS worst case

__global__ __launch_bounds__(256, 3)
void sgemm_bias_kernel(const float* __restrict__ A, const float* __restrict__ W,
                       const float* __restrict__ bias, float* __restrict__ C,
                       int M, int N, int K)
{
    __shared__ float As[16 * ASTRIDE];   // [k][m] transposed
    __shared__ float Bs[16 * 64];        // [k][n]

    const int tid = threadIdx.x;
    const int tx = tid & 15;             // 0..15  -> 4 output cols each
    const int ty = tid >> 4;             // 0..15  -> 8 output rows each
    const int m0 = blockIdx.y * 128;
    const int n0 = blockIdx.x * 64;

    float acc[8][4];
#pragma unroll
    for (int i = 0; i < 8; i++)
#pragma unroll
        for (int j = 0; j < 4; j++) acc[i][j] = 0.f;

    for (int k0 = 0; k0 < K; k0 += 16) {
        // --- load A tile 128x16, store transposed As[k][m] ---
#pragma unroll
        for (int r = 0; r < 2; r++) {
            int f  = tid + r * 256;          // float4 index 0..511
            int mm = f >> 2;                 // 0..127
            int kq = (f & 3) * 4;            // 0,4,8,12
            float4 v = *(const float4*)(A + (size_t)(m0 + mm) * K + k0 + kq);
            As[(kq + 0) * ASTRIDE + mm] = v.x;
            As[(kq + 1) * ASTRIDE + mm] = v.y;
            As[(kq + 2) * ASTRIDE + mm] = v.z;
            As[(kq + 3) * ASTRIDE + mm] = v.w;
        }
        // --- load B tile 16x64 (row-major, direct) ---
        {
            int kk = tid >> 4;               // 0..15
            int nq = (tid & 15) * 4;         // 0..60
            *(float4*)(Bs + kk * 64 + nq) =
                *(const float4*)(W + (size_t)(k0 + kk) * N + n0 + nq);
        }
        __syncthreads();

#pragma unroll
        for (int kk = 0; kk < 16; kk++) {
            float4 b4 = *(const float4*)(Bs + kk * 64 + tx * 4);
            float4 a0 = *(const float4*)(As + kk * ASTRIDE + ty * 8);
            float4 a1 = *(const float4*)(As + kk * ASTRIDE + ty * 8 + 4);
            float a[8] = {a0.x, a0.y, a0.z, a0.w, a1.x, a1.y, a1.z, a1.w};
            float b[4] = {b4.x, b4.y, b4.z, b4.w};
#pragma unroll
            for (int i = 0; i < 8; i++)
#pragma unroll
                for (int j = 0; j < 4; j++)
                    acc[i][j] += a[i] * b[j];
        }
        __syncthreads();
    }

    float4 bv = *(const float4*)(bias + n0 + tx * 4);
#pragma unroll
    for (int i = 0; i < 8; i++) {
        int m = m0 + ty * 8 + i;
        float4 o;
        o.x = acc[i][0] + bv.x;
        o.y = acc[i][1] + bv.y;
        o.z = acc[i][2] + bv.z;
        o.w = acc[i][3] + bv.w;
        *(float4*)(C + (size_t)m * N + n0 + tx * 4) = o;
    }
}

// ---------------------------------------------------------------------------
// Local (banded) attention.
// Grid: (N/64, B*H). Block: 256 threads.
// Each block: 64 queries of one (b,h). Keys span [q0-64, q0+127+64] = 192 rows.
// SMEM: Q[64][64], K[192][68] (padded), V[192][64], S[64][193].
// ---------------------------------------------------------------------------
#define KSTR 68
#define SSTR 193
#define ATT_SMEM ((64*64 + 192*KSTR + 192*64 + 64*SSTR) * sizeof(float))  // 167168 B

__global__ void local_attn_kernel(const float* __restrict__ qkv, float* __restrict__ out)
{
    extern __shared__ float sm[];
    float* Qs = sm;                    // 64*64
    float* Ks = Qs + 64 * 64;          // 192*KSTR
    float* Vs = Ks + 192 * KSTR;       // 192*64
    float* Sc = Vs + 192 * 64;         // 64*SSTR

    const int tid  = threadIdx.x;
    const int bh   = blockIdx.y;
    const int b    = bh / Hh;
    const int h    = bh % Hh;
    const int q0   = blockIdx.x * 64;
    const int k0   = q0 - HALFW;       // absolute index of key row 0 (may be negative)
    const float* base = qkv + (size_t)b * Nn * QKV_COLS;

    // --- load Q tile (64 rows x 64 dims) ---
#pragma unroll
    for (int r = 0; r < 4; r++) {
        int f   = tid + r * 256;       // float4 idx 0..1023
        int row = f >> 4;
        int c4  = (f & 15) * 4;
        float4 v = *(const float4*)(base + (size_t)(q0 + row) * QKV_COLS + h * 64 + c4);
        *(float4*)(Qs + row * 64 + c4) = v;
    }
    // --- load K,V tiles (192 rows, zero-fill out of range) ---
#pragma unroll
    for (int r = 0; r < 12; r++) {
        int f   = tid + r * 256;       // float4 idx 0..3071
        int row = f >> 4;
        int c4  = (f & 15) * 4;
        int t   = k0 + row;
        float4 kv = make_float4(0.f, 0.f, 0.f, 0.f);
        float4 vv = kv;
        if (t >= 0 && t < Nn) {
            const float* rp = base + (size_t)t * QKV_COLS + h * 64 + c4;
            kv = *(const float4*)(rp + Dd);
            vv = *(const float4*)(rp + 2 * Dd);
        }
        *(float4*)(Ks + row * KSTR + c4) = kv;
        *(float4*)(Vs + row * 64 + c4)   = vv;
    }
    __syncthreads();

    // --- scores: S[qi][j] = (q_i . k_j) * scale, masked to band + valid keys ---
    const float scale = 0.125f;  // 1/sqrt(64)
    for (int idx = tid; idx < 64 * 192; idx += 256) {
        int qi = idx / 192;
        int j  = idx % 192;
        float acc = 0.f;
#pragma unroll
        for (int d4 = 0; d4 < 16; d4++) {
            float4 q = *(const float4*)(Qs + qi * 64 + d4 * 4);
            float4 k = *(const float4*)(Ks + j * KSTR + d4 * 4);
            acc += q.x * k.x + q.y * k.y + q.z * k.z + q.w * k.w;
        }
        int t = k0 + j;
        bool valid = (j >= qi) && (j <= qi + 2 * HALFW) && (t >= 0) && (t < Nn);
        Sc[qi * SSTR + j] = valid ? acc * scale : -1e30f;
    }
    __syncthreads();

    // --- softmax per query row (one warp per row, 8 rows/warp) ---
    const int warp = tid >> 5;
    const int lane = tid & 31;
    for (int r = warp; r < 64; r += 8) {
        float m = -1e30f;
        for (int j = lane; j < 192; j += 32) m = fmaxf(m, Sc[r * SSTR + j]);
#pragma unroll
        for (int o = 16; o > 0; o >>= 1) m = fmaxf(m, __shfl_xor_sync(0xffffffffu, m, o));
        float s = 0.f;
        for (int j = lane; j < 192; j += 32) {
            float e = __expf(Sc[r * SSTR + j] - m);
            Sc[r * SSTR + j] = e;
            s += e;
        }
#pragma unroll
        for (int o = 16; o > 0; o >>= 1) s += __shfl_xor_sync(0xffffffffu, s, o);
        float inv = 1.f / s;
        for (int j = lane; j < 192; j += 32) Sc[r * SSTR + j] *= inv;
    }
    __syncthreads();

    // --- PV: out[qi][d] = sum_{j in band} p * V[j][d]  (band: j in [qi, qi+128]) ---
    for (int idx = tid; idx < 64 * 16; idx += 256) {
        int qi = idx >> 4;
        int d4 = (idx & 15) * 4;
        float4 o = make_float4(0.f, 0.f, 0.f, 0.f);
        const float* srow = Sc + qi * SSTR;
#pragma unroll 4
        for (int j = qi; j <= qi + 2 * HALFW; j++) {
            float p = srow[j];
            float4 v = *(const float4*)(Vs + j * 64 + d4);
            o.x += p * v.x; o.y += p * v.y; o.z += p * v.z; o.w += p * v.w;
        }
        *(float4*)(out + (size_t)(b * Nn + q0 + qi) * Dd + h * 64 + d4) = o;
    }
}

// ---------------------------------------------------------------------------
extern "C" void kernel_launch(void* const* d_in, const int* in_sizes, int n_in,
                              void* d_out, int out_size)
{
    const float* x    = (const float*)d_in[0];
    const float* Wqkv = (const float*)d_in[1];
    const float* bqkv = (const float*)d_in[2];
    const float* Wout = (const float*)d_in[3];
    const float* bout = (const float*)d_in[4];
    float* out = (float*)d_out;

    float* qkv = nullptr;
    float* att = nullptr;
    cudaGetSymbolAddress((void**)&qkv, g_qkv);
    cudaGetSymbolAddress((void**)&att, g_att);

    const int M = Bb * Nn;   // 4096

    // 1) QKV projection: [4096,1024] @ [1024,3072] + bqkv
    {
        dim3 grid(QKV_COLS / 64, M / 128);
        sgemm_bias_kernel<<<grid, 256>>>(x, Wqkv, bqkv, qkv, M, QKV_COLS, Dd);
    }

    // 2) Banded local attention
    {
        cudaFuncSetAttribute(local_attn_kernel,
                             cudaFuncAttributeMaxDynamicSharedMemorySize,
                             (int)ATT_SMEM);
        dim3 grid(Nn / 64, Bb * Hh);
        local_attn_kernel<<<grid, 256, ATT_SMEM>>>(qkv, att);
    }

    // 3) Output projection: [4096,1024] @ [1024,1024] + bout
    {
        dim3 grid(Dd / 64, M / 128);
        sgemm_bias_kernel<<<grid, 256>>>(att, Wout, bout, out, M, Dd, Dd);
    }
}

// round 4
// speedup vs baseline: 1.8988x; 1.8988x over previous
#include <cuda_runtime.h>
#include <cstdint>

// Problem constants
#define Bb   2
#define Nn   2048
#define Dd   1024
#define Hh   16
#define HALFW 64
#define QKV_COLS (3*Dd)   // 3072
#define Mrows (Bb*Nn)     // 4096

// Scratch (device globals; no allocation allowed)
__device__ float g_qkv[(size_t)Mrows*QKV_COLS];   // [4096, 3072]
__device__ float g_att[(size_t)Mrows*Dd];         // [4096, 1024] (tf32-rounded)
__device__ float g_xr [(size_t)Mrows*Dd];         // x rounded to tf32
__device__ float g_Wqkv_r[(size_t)Dd*QKV_COLS];   // Wqkv rounded (same layout)
__device__ float g_Wout_r[(size_t)Dd*Dd];         // Wout rounded

// ---------------------------------------------------------------------------
__device__ __forceinline__ uint32_t smem_u32(const void* p) {
    uint32_t a;
    asm("{ .reg .u64 t; cvta.to.shared.u64 t, %1; cvt.u32.u64 %0, t; }"
        : "=r"(a) : "l"(p));
    return a;
}
__device__ __forceinline__ float rna_tf32(float x) {
    float r; asm("cvt.rna.tf32.f32 %0, %1;" : "=f"(r) : "f"(x)); return r;
}

// ---------------------------------------------------------------------------
// tf32 mma.sync GEMM: C[M,N] = A[M,K] @ W[K,N] + bias[N]
// BM=BN=128, BK=16, 3-stage cp.async, 256 threads, warp tile 64x32.
// A and W pre-rounded to tf32 (rna).
// ---------------------------------------------------------------------------
#define BM 128
#define BN 128
#define BK 16
#define STAGES 3
#define ASTR 36    // A smem row stride (floats): bank-conflict-free frag loads
#define BSTR 136   // B smem row stride (floats)
#define STAGE_FLOATS (BM*ASTR + BK*BSTR)   // 4608 + 2176 = 6784
#define GEMM_SMEM (STAGES*STAGE_FLOATS*4)  // 81408 B

__device__ __forceinline__ void g_load_stage(uint32_t sbase,
                                             const float* __restrict__ A,
                                             const float* __restrict__ W,
                                             int m0, int n0, int k0,
                                             int N, int K, int tid)
{
    // A tile: 128 rows x 16 k, row-major stride ASTR
#pragma unroll
    for (int i = 0; i < 2; i++) {
        int c  = tid + i * 256;          // 0..511 chunks of 16B
        int mm = c >> 2, ch = c & 3;
        uint32_t dst = sbase + (uint32_t)(mm * ASTR + ch * 4) * 4u;
        const float* src = A + (size_t)(m0 + mm) * K + k0 + ch * 4;
        asm volatile("cp.async.cg.shared.global [%0], [%1], 16;" :: "r"(dst), "l"(src));
    }
    // B tile: 16 k-rows x 128 n, k-major stride BSTR (W is [K,N] row-major)
    uint32_t bb = sbase + (uint32_t)(BM * ASTR) * 4u;
#pragma unroll
    for (int i = 0; i < 2; i++) {
        int c  = tid + i * 256;          // 0..511
        int kr = c >> 5, ch = c & 31;
        uint32_t dst = bb + (uint32_t)(kr * BSTR + ch * 4) * 4u;
        const float* src = W + (size_t)(k0 + kr) * N + n0 + ch * 4;
        asm volatile("cp.async.cg.shared.global [%0], [%1], 16;" :: "r"(dst), "l"(src));
    }
    asm volatile("cp.async.commit_group;" ::: "memory");
}

__global__ __launch_bounds__(256, 2)
void tf32_mma_gemm(const float* __restrict__ A, const float* __restrict__ W,
                   const float* __restrict__ bias, float* __restrict__ C,
                   int M, int N, int K)
{
    extern __shared__ float sm[];
    const int tid  = threadIdx.x;
    const int wid  = tid >> 5;
    const int lane = tid & 31;
    const int g    = lane >> 2;          // group id 0..7
    const int t4   = lane & 3;           // thread-in-group 0..3
    const int m0 = blockIdx.y * BM;
    const int n0 = blockIdx.x * BN;
    const int wm = (wid >> 2) * 64;      // warp M offset within tile
    const int wn = (wid & 3) * 32;       // warp N offset within tile
    const uint32_t smb = smem_u32(sm);

    float acc[4][4][4];
#pragma unroll
    for (int i = 0; i < 4; i++)
#pragma unroll
        for (int j = 0; j < 4; j++)
#pragma unroll
            for (int q = 0; q < 4; q++) acc[i][j][q] = 0.f;

    const int NITER = K / BK;

    // Prologue
#pragma unroll
    for (int s = 0; s < STAGES - 1; s++)
        g_load_stage(smb + (uint32_t)(s * STAGE_FLOATS) * 4u, A, W, m0, n0, s * BK, N, K, tid);

    for (int it = 0; it < NITER; it++) {
        asm volatile("cp.async.wait_group %0;" :: "n"(STAGES - 2) : "memory");
        __syncthreads();

        if (it + STAGES - 1 < NITER) {
            int ps = (it + STAGES - 1) % STAGES;
            g_load_stage(smb + (uint32_t)(ps * STAGE_FLOATS) * 4u, A, W,
                         m0, n0, (it + STAGES - 1) * BK, N, K, tid);
        }

        const float* As = sm + (it % STAGES) * STAGE_FLOATS;
        const float* Bs = As + BM * ASTR;
        const uint32_t* Au = (const uint32_t*)As;
        const uint32_t* Bu = (const uint32_t*)Bs;

#pragma unroll
        for (int kk = 0; kk < BK; kk += 8) {
            uint32_t a[4][4], b[4][2];
#pragma unroll
            for (int mt = 0; mt < 4; mt++) {
                int r = wm + mt * 16 + g;
                a[mt][0] = Au[r * ASTR + kk + t4];
                a[mt][1] = Au[(r + 8) * ASTR + kk + t4];
                a[mt][2] = Au[r * ASTR + kk + t4 + 4];
                a[mt][3] = Au[(r + 8) * ASTR + kk + t4 + 4];
            }
#pragma unroll
            for (int nt = 0; nt < 4; nt++) {
                int cn = wn + nt * 8 + g;
                b[nt][0] = Bu[(kk + t4) * BSTR + cn];
                b[nt][1] = Bu[(kk + t4 + 4) * BSTR + cn];
            }
#pragma unroll
            for (int mt = 0; mt < 4; mt++)
#pragma unroll
                for (int nt = 0; nt < 4; nt++) {
                    asm volatile(
                        "mma.sync.aligned.m16n8k8.row.col.f32.tf32.tf32.f32 "
                        "{%0,%1,%2,%3}, {%4,%5,%6,%7}, {%8,%9}, {%0,%1,%2,%3};"
                        : "+f"(acc[mt][nt][0]), "+f"(acc[mt][nt][1]),
                          "+f"(acc[mt][nt][2]), "+f"(acc[mt][nt][3])
                        : "r"(a[mt][0]), "r"(a[mt][1]), "r"(a[mt][2]), "r"(a[mt][3]),
                          "r"(b[nt][0]), "r"(b[nt][1]));
                }
        }
    }

    // Epilogue: direct float2 stores with bias
#pragma unroll
    for (int nt = 0; nt < 4; nt++) {
        int cc = n0 + wn + nt * 8 + 2 * t4;
        float2 bv = *(const float2*)(bias + cc);
#pragma unroll
        for (int mt = 0; mt < 4; mt++) {
            int r0 = m0 + wm + mt * 16 + g;
            float2 o0, o1;
            o0.x = acc[mt][nt][0] + bv.x;  o0.y = acc[mt][nt][1] + bv.y;
            o1.x = acc[mt][nt][2] + bv.x;  o1.y = acc[mt][nt][3] + bv.y;
            *(float2*)(C + (size_t)r0 * N + cc)       = o0;
            *(float2*)(C + (size_t)(r0 + 8) * N + cc) = o1;
        }
    }
}

// ---------------------------------------------------------------------------
// Pre-pass: tf32 rounding (rna)
// ---------------------------------------------------------------------------
__global__ void round_tf32_kernel(const float* __restrict__ in, float* __restrict__ out, int n4)
{
    int i = blockIdx.x * blockDim.x + threadIdx.x;
    if (i < n4) {
        float4 v = ((const float4*)in)[i];
        v.x = rna_tf32(v.x); v.y = rna_tf32(v.y);
        v.z = rna_tf32(v.z); v.w = rna_tf32(v.w);
        ((float4*)out)[i] = v;
    }
}

// ---------------------------------------------------------------------------
// Local (banded) attention — fp32, output rounded to tf32.
// ---------------------------------------------------------------------------
#define KSTR 68
#define SSTR 193
#define ATT_SMEM ((64*64 + 192*KSTR + 192*64 + 64*SSTR) * sizeof(float))

__global__ void local_attn_kernel(const float* __restrict__ qkv, float* __restrict__ out)
{
    extern __shared__ float sm[];
    float* Qs = sm;
    float* Ks = Qs + 64 * 64;
    float* Vs = Ks + 192 * KSTR;
    float* Sc = Vs + 192 * 64;

    const int tid  = threadIdx.x;
    const int bh   = blockIdx.y;
    const int b    = bh / Hh;
    const int h    = bh % Hh;
    const int q0   = blockIdx.x * 64;
    const int k0   = q0 - HALFW;
    const float* base = qkv + (size_t)b * Nn * QKV_COLS;

#pragma unroll
    for (int r = 0; r < 4; r++) {
        int f   = tid + r * 256;
        int row = f >> 4;
        int c4  = (f & 15) * 4;
        float4 v = *(const float4*)(base + (size_t)(q0 + row) * QKV_COLS + h * 64 + c4);
        *(float4*)(Qs + row * 64 + c4) = v;
    }
#pragma unroll
    for (int r = 0; r < 12; r++) {
        int f   = tid + r * 256;
        int row = f >> 4;
        int c4  = (f & 15) * 4;
        int t   = k0 + row;
        float4 kv = make_float4(0.f, 0.f, 0.f, 0.f);
        float4 vv = kv;
        if (t >= 0 && t < Nn) {
            const float* rp = base + (size_t)t * QKV_COLS + h * 64 + c4;
            kv = *(const float4*)(rp + Dd);
            vv = *(const float4*)(rp + 2 * Dd);
        }
        *(float4*)(Ks + row * KSTR + c4) = kv;
        *(float4*)(Vs + row * 64 + c4)   = vv;
    }
    __syncthreads();

    const float scale = 0.125f;
    for (int idx = tid; idx < 64 * 192; idx += 256) {
        int qi = idx / 192;
        int j  = idx % 192;
        float acc = 0.f;
#pragma unroll
        for (int d4 = 0; d4 < 16; d4++) {
            float4 q = *(const float4*)(Qs + qi * 64 + d4 * 4);
            float4 k = *(const float4*)(Ks + j * KSTR + d4 * 4);
            acc += q.x * k.x + q.y * k.y + q.z * k.z + q.w * k.w;
        }
        int t = k0 + j;
        bool valid = (j >= qi) && (j <= qi + 2 * HALFW) && (t >= 0) && (t < Nn);
        Sc[qi * SSTR + j] = valid ? acc * scale : -1e30f;
    }
    __syncthreads();

    const int warp = tid >> 5;
    const int lane = tid & 31;
    for (int r = warp; r < 64; r += 8) {
        float m = -1e30f;
        for (int j = lane; j < 192; j += 32) m = fmaxf(m, Sc[r * SSTR + j]);
#pragma unroll
        for (int o = 16; o > 0; o >>= 1) m = fmaxf(m, __shfl_xor_sync(0xffffffffu, m, o));
        float s = 0.f;
        for (int j = lane; j < 192; j += 32) {
            float e = __expf(Sc[r * SSTR + j] - m);
            Sc[r * SSTR + j] = e;
            s += e;
        }
#pragma unroll
        for (int o = 16; o > 0; o >>= 1) s += __shfl_xor_sync(0xffffffffu, s, o);
        float inv = 1.f / s;
        for (int j = lane; j < 192; j += 32) Sc[r * SSTR + j] *= inv;
    }
    __syncthreads();

    for (int idx = tid; idx < 64 * 16; idx += 256) {
        int qi = idx >> 4;
        int d4 = (idx & 15) * 4;
        float4 o = make_float4(0.f, 0.f, 0.f, 0.f);
        const float* srow = Sc + qi * SSTR;
#pragma unroll 4
        for (int j = qi; j <= qi + 2 * HALFW; j++) {
            float p = srow[j];
            float4 v = *(const float4*)(Vs + j * 64 + d4);
            o.x += p * v.x; o.y += p * v.y; o.z += p * v.z; o.w += p * v.w;
        }
        o.x = rna_tf32(o.x); o.y = rna_tf32(o.y);
        o.z = rna_tf32(o.z); o.w = rna_tf32(o.w);
        *(float4*)(out + (size_t)(b * Nn + q0 + qi) * Dd + h * 64 + d4) = o;
    }
}

// ---------------------------------------------------------------------------
extern "C" void kernel_launch(void* const* d_in, const int* in_sizes, int n_in,
                              void* d_out, int out_size)
{
    const float* x    = (const float*)d_in[0];
    const float* Wqkv = (const float*)d_in[1];
    const float* bqkv = (const float*)d_in[2];
    const float* Wout = (const float*)d_in[3];
    const float* bout = (const float*)d_in[4];
    float* out = (float*)d_out;

    float *qkv, *att, *xr, *Wr1, *Wr2;
    cudaGetSymbolAddress((void**)&qkv, g_qkv);
    cudaGetSymbolAddress((void**)&att, g_att);
    cudaGetSymbolAddress((void**)&xr,  g_xr);
    cudaGetSymbolAddress((void**)&Wr1, g_Wqkv_r);
    cudaGetSymbolAddress((void**)&Wr2, g_Wout_r);

    // Pre-passes: tf32 rounding
    {
        int n4;
        n4 = Mrows * Dd / 4;
        round_tf32_kernel<<<(n4 + 255) / 256, 256>>>(x, xr, n4);
        n4 = Dd * QKV_COLS / 4;
        round_tf32_kernel<<<(n4 + 255) / 256, 256>>>(Wqkv, Wr1, n4);
        n4 = Dd * Dd / 4;
        round_tf32_kernel<<<(n4 + 255) / 256, 256>>>(Wout, Wr2, n4);
    }

    // 1) QKV projection (tensor tf32)
    {
        cudaFuncSetAttribute(tf32_mma_gemm,
                             cudaFuncAttributeMaxDynamicSharedMemorySize, GEMM_SMEM);
        dim3 grid(QKV_COLS / BN, Mrows / BM);  // 24 x 32
        tf32_mma_gemm<<<grid, 256, GEMM_SMEM>>>(xr, Wr1, bqkv, qkv, Mrows, QKV_COLS, Dd);
    }

    // 2) Banded local attention (fp32)
    {
        cudaFuncSetAttribute(local_attn_kernel,
                             cudaFuncAttributeMaxDynamicSharedMemorySize, (int)ATT_SMEM);
        dim3 grid(Nn / 64, Bb * Hh);
        local_attn_kernel<<<grid, 256, ATT_SMEM>>>(qkv, att);
    }

    // 3) Output projection (tensor tf32)
    {
        dim3 grid(Dd / BN, Mrows / BM);        // 8 x 32
        tf32_mma_gemm<<<grid, 256, GEMM_SMEM>>>(att, Wr2, bout, out, Mrows, Dd, Dd);
    }
}